// round 9
// baseline (speedup 1.0000x reference)
#include <cuda_runtime.h>

#define D 128
#define N_ING 100000
#define N_TASTE 50000
#define E_EDGES 600000
#define NEG_SLOPE 0.2f
#define CAP 64          // per-dst bucket capacity; deg ~ Poisson(12), P(>64) < 1e-20

// ---------------- scratch (device globals) ----------------
__device__ float g_v_src[D];
__device__ float g_v_dst[D];
__device__ float g_c_src, g_c_dst;
__device__ float g_a_src[N_ING];
__device__ float g_a_dst[N_TASTE];
__device__ int   g_cnt[N_TASTE];                   // degree cursor / epilogue mask
__device__ int2  g_slot[(size_t)N_TASTE * CAP];    // (src, exp-weight bits) buckets
__device__ float g_whi[D * D];                     // W_ing hi tf32 part
__device__ float g_wlo[D * D];                     // W_ing lo tf32 part

// ---------------- tf32 helpers ----------------
__device__ __forceinline__ void split_tf32(float x, unsigned& hi, unsigned& lo) {
    asm("cvt.rna.tf32.f32 %0, %1;" : "=r"(hi) : "f"(x));
    float lof = x - __uint_as_float(hi);
    asm("cvt.rna.tf32.f32 %0, %1;" : "=r"(lo) : "f"(lof));
}
__device__ __forceinline__ void mma_tf32(float* c,
                                         unsigned a0, unsigned a1, unsigned a2, unsigned a3,
                                         unsigned b0, unsigned b1) {
    asm volatile("mma.sync.aligned.m16n8k8.row.col.f32.tf32.tf32.f32 "
                 "{%0,%1,%2,%3}, {%4,%5,%6,%7}, {%8,%9}, {%0,%1,%2,%3};"
                 : "+f"(c[0]), "+f"(c[1]), "+f"(c[2]), "+f"(c[3])
                 : "r"(a0), "r"(a1), "r"(a2), "r"(a3), "r"(b0), "r"(b1));
}

// ---------------- K0: warp-per-row  v = W @ att  (+ bias dots) -------------
__global__ void k0_prep(const float* __restrict__ W_ing,  const float* __restrict__ b_ing,
                        const float* __restrict__ W_taste,const float* __restrict__ b_taste,
                        const float* __restrict__ att_src,const float* __restrict__ att_dst) {
    int w    = (blockIdx.x * blockDim.x + threadIdx.x) >> 5;
    int lane = threadIdx.x & 31;
    if (w >= 258) return;
    const float* vecA;
    const float* vecB;
    if (w < 128)      { vecA = W_ing   + w * D;         vecB = att_src; }
    else if (w < 256) { vecA = W_taste + (w - 128) * D; vecB = att_dst; }
    else if (w == 256){ vecA = b_ing;                   vecB = att_src; }
    else              { vecA = b_taste;                 vecB = att_dst; }
    float4 a = ((const float4*)vecA)[lane];
    float4 c = ((const float4*)vecB)[lane];
    float s = a.x * c.x + a.y * c.y + a.z * c.z + a.w * c.w;
    #pragma unroll
    for (int o = 16; o; o >>= 1) s += __shfl_down_sync(0xffffffffu, s, o);
    if (lane == 0) {
        if (w < 128)       g_v_src[w] = s;
        else if (w < 256)  g_v_dst[w - 128] = s;
        else if (w == 256) g_c_src = s;
        else               g_c_dst = s;
    }
}

// ---------------- dots: a_src then a_dst; 4 rows/warp (37500 warps) --------
__global__ void k_dots(const float* __restrict__ x_ing, const float* __restrict__ x_taste) {
    int warp = (blockIdx.x * blockDim.x + threadIdx.x) >> 5;
    int lane = threadIdx.x & 31;
    int row0 = warp * 4;
    bool ing = row0 < N_ING;
    int base = ing ? row0 : row0 - N_ING;
    if (!ing && base >= N_TASTE) return;
    const float4* x4 = (const float4*)(ing ? x_ing : x_taste);
    float4 vv = ing ? ((const float4*)g_v_src)[lane] : ((const float4*)g_v_dst)[lane];
    float  cc = ing ? g_c_src : g_c_dst;
    float* outp = ing ? g_a_src : g_a_dst;
    float4 xv[4];
    #pragma unroll
    for (int r = 0; r < 4; r++) xv[r] = x4[(size_t)(base + r) * 32 + lane];
    #pragma unroll
    for (int r = 0; r < 4; r++) {
        float s = xv[r].x * vv.x + xv[r].y * vv.y + xv[r].z * vv.z + xv[r].w * vv.w;
        #pragma unroll
        for (int o = 16; o; o >>= 1) s += __shfl_down_sync(0xffffffffu, s, o);
        if (lane == 0) outp[base + r] = s + cc;
    }
}

// ---------------- stream B: split W, zero counters, out_ing copy -----------
__global__ void k_splitW(const float* __restrict__ W) {
    int i = blockIdx.x * blockDim.x + threadIdx.x;
    if (i >= D * D) return;
    unsigned hi, lo;
    split_tf32(W[i], hi, lo);
    g_whi[i] = __uint_as_float(hi);
    g_wlo[i] = __uint_as_float(lo);
}

__global__ void k_zero() {
    int i = blockIdx.x * blockDim.x + threadIdx.x;
    if (i < N_TASTE) g_cnt[i] = 0;
}

__global__ void k_copy(const float4* __restrict__ src, float4* __restrict__ dst) {
    int i = blockIdx.x * blockDim.x + threadIdx.x;
    int n = N_ING * 32;
    int stride = gridDim.x * blockDim.x;
    for (; i < n; i += stride) dst[i] = src[i];
}

// ---------------- fill: bucket edges, packed 8B stores ---------------------
__global__ void k_fill(const int* __restrict__ src, const int* __restrict__ dst) {
    int e = blockIdx.x * blockDim.x + threadIdx.x;
    if (e >= E_EDGES) return;
    int si = src[e];
    int t  = dst[e];
    float l = g_a_src[si] + g_a_dst[t];
    l = l > 0.f ? l : NEG_SLOPE * l;
    int pos = atomicAdd(&g_cnt[t], 1);
    g_slot[(size_t)t * CAP + pos] = make_int2(si, __float_as_int(__expf(l)));
}

// ---------------- fused: gather -> smem -> TF32 3-pass MMA -> epilogue -----
// TM=128 rows/block, warp owns 16-row x 128-col tile.
// smem: W_hi[128][132] + W_lo[128][132] + xs[128][132]  = 198KB
#define TM 128
#define SROW 132
__global__ void __launch_bounds__(256) k_fused(const float* __restrict__ bias,
                                               const float* __restrict__ x_ing,
                                               const float* __restrict__ x_taste,
                                               float* __restrict__ out_taste) {
    extern __shared__ float sm[];
    float* whs = sm;                    // [128][SROW] hi
    float* wls = sm + D * SROW;         // [128][SROW] lo
    float* xs  = sm + 2 * D * SROW;     // [TM][SROW]
    float4* xs4 = (float4*)xs;          // row stride = 33 float4
    int tid  = threadIdx.x;
    int lane = tid & 31;
    int wrp  = tid >> 5;
    int row0 = blockIdx.x * TM;
    const float4* x4 = (const float4*)x_ing;

    // ---- stage pre-split W ----
    for (int i = tid; i < D * D; i += 256) {
        int k = i >> 7, n = i & 127;
        whs[k * SROW + n] = g_whi[i];
        wls[k * SROW + n] = g_wlo[i];
    }

    // ---- gather: 16 rows per warp ----
    #pragma unroll 1
    for (int i = 0; i < 16; i++) {
        int r = wrp * 16 + i;
        int t = row0 + r;
        float4 acc = make_float4(0.f, 0.f, 0.f, 0.f);
        float wsum = 0.f;
        if (t < N_TASTE) {
            int n = g_cnt[t];
            const int2* sp = g_slot + (size_t)t * CAP;
            int e = 0;
            for (; e + 4 <= n; e += 4) {
                int2 e0 = sp[e], e1 = sp[e+1], e2 = sp[e+2], e3 = sp[e+3];
                float w0 = __int_as_float(e0.y), w1 = __int_as_float(e1.y);
                float w2 = __int_as_float(e2.y), w3 = __int_as_float(e3.y);
                float4 v0 = x4[(size_t)e0.x * 32 + lane];
                float4 v1 = x4[(size_t)e1.x * 32 + lane];
                float4 v2 = x4[(size_t)e2.x * 32 + lane];
                float4 v3 = x4[(size_t)e3.x * 32 + lane];
                wsum  += w0 + w1 + w2 + w3;
                acc.x += w0*v0.x + w1*v1.x + w2*v2.x + w3*v3.x;
                acc.y += w0*v0.y + w1*v1.y + w2*v2.y + w3*v3.y;
                acc.z += w0*v0.z + w1*v1.z + w2*v2.z + w3*v3.z;
                acc.w += w0*v0.w + w1*v1.w + w2*v2.w + w3*v3.w;
            }
            for (; e < n; e++) {
                int2 ee = sp[e];
                float w = __int_as_float(ee.y);
                float4 v = x4[(size_t)ee.x * 32 + lane];
                wsum += w;
                acc.x += w*v.x; acc.y += w*v.y; acc.z += w*v.z; acc.w += w*v.w;
            }
        }
        float inv = 1.f / (wsum + 1e-16f);
        acc.x *= inv; acc.y *= inv; acc.z *= inv; acc.w *= inv;
        xs4[r * 33 + lane] = acc;
    }
    __syncthreads();   // W staged + all rows visible

    // ---- GEMM: tf32 3-pass; warp = 16 rows x 128 cols ----
    int g = lane >> 2, t4 = lane & 3;
    int rbase = wrp * 16;
    float acc[16][4];
    #pragma unroll
    for (int nn = 0; nn < 16; nn++)
        #pragma unroll
        for (int j = 0; j < 4; j++) acc[nn][j] = 0.f;

    #pragma unroll 1
    for (int kk = 0; kk < 16; kk++) {
        int k0 = kk * 8;
        unsigned a0h,a0l,a1h,a1l,a2h,a2l,a3h,a3l;
        split_tf32(xs[(rbase+g  ) * SROW + k0 + t4    ], a0h, a0l);
        split_tf32(xs[(rbase+g+8) * SROW + k0 + t4    ], a1h, a1l);
        split_tf32(xs[(rbase+g  ) * SROW + k0 + t4 + 4], a2h, a2l);
        split_tf32(xs[(rbase+g+8) * SROW + k0 + t4 + 4], a3h, a3l);
        #pragma unroll
        for (int nn = 0; nn < 16; nn++) {
            int col = nn * 8 + g;
            unsigned b0h = __float_as_uint(whs[(k0 + t4    ) * SROW + col]);
            unsigned b1h = __float_as_uint(whs[(k0 + t4 + 4) * SROW + col]);
            unsigned b0l = __float_as_uint(wls[(k0 + t4    ) * SROW + col]);
            unsigned b1l = __float_as_uint(wls[(k0 + t4 + 4) * SROW + col]);
            mma_tf32(acc[nn], a0h,a1h,a2h,a3h, b0h,b1h);   // hi*hi
            mma_tf32(acc[nn], a0h,a1h,a2h,a3h, b0l,b1l);   // hi*lo
            mma_tf32(acc[nn], a0l,a1l,a2l,a3l, b0h,b1h);   // lo*hi
        }
    }

    // ---- epilogue: relu + blend ----
    int grow0 = row0 + rbase + g;
    int grow1 = grow0 + 8;
    float has0 = (grow0 < N_TASTE && g_cnt[grow0] > 0) ? 1.f : 0.f;
    float has1 = (grow1 < N_TASTE && g_cnt[grow1] > 0) ? 1.f : 0.f;
    #pragma unroll
    for (int nn = 0; nn < 16; nn++) {
        int col = nn * 8 + 2 * t4;
        float2 bj = *(const float2*)(bias + col);
        if (grow0 < N_TASTE) {
            float2 xt = *(const float2*)(x_taste + (size_t)grow0 * D + col);
            float2 o;
            o.x = fmaxf(has0 * (acc[nn][0] + bj.x), 0.f) * 0.5f + 0.5f * xt.x;
            o.y = fmaxf(has0 * (acc[nn][1] + bj.y), 0.f) * 0.5f + 0.5f * xt.y;
            *(float2*)(out_taste + (size_t)grow0 * D + col) = o;
        }
        if (grow1 < N_TASTE) {
            float2 xt = *(const float2*)(x_taste + (size_t)grow1 * D + col);
            float2 o;
            o.x = fmaxf(has1 * (acc[nn][2] + bj.x), 0.f) * 0.5f + 0.5f * xt.x;
            o.y = fmaxf(has1 * (acc[nn][3] + bj.y), 0.f) * 0.5f + 0.5f * xt.y;
            *(float2*)(out_taste + (size_t)grow1 * D + col) = o;
        }
    }
}

// ---------------- launcher (fork/join capture pattern) ----------------
extern "C" void kernel_launch(void* const* d_in, const int* in_sizes, int n_in,
                              void* d_out, int out_size) {
    const float* x_ing   = (const float*)d_in[0];
    const float* x_taste = (const float*)d_in[1];
    const float* W_ing   = (const float*)d_in[2];
    const float* b_ing   = (const float*)d_in[3];
    const float* W_taste = (const float*)d_in[4];
    const float* b_taste = (const float*)d_in[5];
    const float* att_src = (const float*)d_in[6];
    const float* att_dst = (const float*)d_in[7];
    // d_in[8..10] (Wk, bk, q): softmax over single metapath == 1.0 -> dead code
    const int* src_idx = (const int*)d_in[11];
    const int* dst_idx = (const int*)d_in[12];

    float* out       = (float*)d_out;
    float* out_ing   = out;                      // [N_ING, D] == x_ing
    float* out_taste = out + (size_t)N_ING * D;  // [N_TASTE, D]

    static const int SMEM_FUSED = (2 * D + TM) * SROW * (int)sizeof(float);  // 202752

    static cudaStream_t sB = nullptr;
    static cudaEvent_t  evFork = nullptr, evZero = nullptr, evCopy = nullptr;
    if (sB == nullptr) {
        cudaStreamCreateWithFlags(&sB, cudaStreamNonBlocking);
        cudaEventCreateWithFlags(&evFork, cudaEventDisableTiming);
        cudaEventCreateWithFlags(&evZero, cudaEventDisableTiming);
        cudaEventCreateWithFlags(&evCopy, cudaEventDisableTiming);
        cudaFuncSetAttribute(k_fused, cudaFuncAttributeMaxDynamicSharedMemorySize, SMEM_FUSED);
    }

    // fork stream B: W split + zero counters + out_ing copy (all off critical path)
    cudaEventRecord(evFork, 0);
    cudaStreamWaitEvent(sB, evFork, 0);
    k_splitW<<<(D * D + 255) / 256, 256, 0, sB>>>(W_ing);
    k_zero<<<(N_TASTE + 1023) / 1024, 1024, 0, sB>>>();
    cudaEventRecord(evZero, sB);                 // covers splitW + zero
    k_copy<<<1024, 256, 0, sB>>>((const float4*)x_ing, (float4*)out_ing);
    cudaEventRecord(evCopy, sB);

    // stream A (default): critical path
    k0_prep<<<33, 256>>>(W_ing, b_ing, W_taste, b_taste, att_src, att_dst);
    k_dots<<<4688, 256>>>(x_ing, x_taste);
    cudaStreamWaitEvent(0, evZero, 0);
    k_fill<<<(E_EDGES + 255) / 256, 256>>>(src_idx, dst_idx);
    k_fused<<<(N_TASTE + TM - 1) / TM, 256, SMEM_FUSED>>>(b_ing, x_ing, x_taste, out_taste);
    cudaStreamWaitEvent(0, evCopy, 0);           // join copy before graph end
}

// round 10
// speedup vs baseline: 1.2889x; 1.2889x over previous
#include <cuda_runtime.h>

#define D 128
#define N_ING 100000
#define N_TASTE 50000
#define E_EDGES 600000
#define NEG_SLOPE 0.2f
#define CAP 64          // per-dst bucket capacity; deg ~ Poisson(12), P(>64) < 1e-20

// ---------------- scratch (device globals) ----------------
__device__ float g_v_src[D];
__device__ float g_v_dst[D];
__device__ float g_c_src, g_c_dst;
__device__ float g_a_src[N_ING];
__device__ float g_a_dst[N_TASTE];
__device__ int   g_cnt[N_TASTE];                   // degree cursor / epilogue mask
__device__ int2  g_slot[(size_t)N_TASTE * CAP];    // (src, exp-weight bits) buckets
__device__ float g_whi[D * D];                     // W_ing hi tf32 part
__device__ float g_wlo[D * D];                     // W_ing lo tf32 part
__device__ float g_gbuf[(size_t)N_TASTE * D];      // aggregated rows (25.6MB)

// ---------------- tf32 helpers ----------------
__device__ __forceinline__ void split_tf32(float x, unsigned& hi, unsigned& lo) {
    asm("cvt.rna.tf32.f32 %0, %1;" : "=r"(hi) : "f"(x));
    float lof = x - __uint_as_float(hi);
    asm("cvt.rna.tf32.f32 %0, %1;" : "=r"(lo) : "f"(lof));
}
__device__ __forceinline__ void mma_tf32(float* c,
                                         unsigned a0, unsigned a1, unsigned a2, unsigned a3,
                                         unsigned b0, unsigned b1) {
    asm volatile("mma.sync.aligned.m16n8k8.row.col.f32.tf32.tf32.f32 "
                 "{%0,%1,%2,%3}, {%4,%5,%6,%7}, {%8,%9}, {%0,%1,%2,%3};"
                 : "+f"(c[0]), "+f"(c[1]), "+f"(c[2]), "+f"(c[3])
                 : "r"(a0), "r"(a1), "r"(a2), "r"(a3), "r"(b0), "r"(b1));
}

// ---------------- K0: warp-per-row  v = W @ att  (+ bias dots) -------------
__global__ void k0_prep(const float* __restrict__ W_ing,  const float* __restrict__ b_ing,
                        const float* __restrict__ W_taste,const float* __restrict__ b_taste,
                        const float* __restrict__ att_src,const float* __restrict__ att_dst) {
    int w    = (blockIdx.x * blockDim.x + threadIdx.x) >> 5;
    int lane = threadIdx.x & 31;
    if (w >= 258) return;
    const float* vecA;
    const float* vecB;
    if (w < 128)      { vecA = W_ing   + w * D;         vecB = att_src; }
    else if (w < 256) { vecA = W_taste + (w - 128) * D; vecB = att_dst; }
    else if (w == 256){ vecA = b_ing;                   vecB = att_src; }
    else              { vecA = b_taste;                 vecB = att_dst; }
    float4 a = ((const float4*)vecA)[lane];
    float4 c = ((const float4*)vecB)[lane];
    float s = a.x * c.x + a.y * c.y + a.z * c.z + a.w * c.w;
    #pragma unroll
    for (int o = 16; o; o >>= 1) s += __shfl_down_sync(0xffffffffu, s, o);
    if (lane == 0) {
        if (w < 128)       g_v_src[w] = s;
        else if (w < 256)  g_v_dst[w - 128] = s;
        else if (w == 256) g_c_src = s;
        else               g_c_dst = s;
    }
}

// ---------------- dots: a_src then a_dst; 4 rows/warp (37500 warps) --------
__global__ void k_dots(const float* __restrict__ x_ing, const float* __restrict__ x_taste) {
    int warp = (blockIdx.x * blockDim.x + threadIdx.x) >> 5;
    int lane = threadIdx.x & 31;
    int row0 = warp * 4;
    bool ing = row0 < N_ING;
    int base = ing ? row0 : row0 - N_ING;
    if (!ing && base >= N_TASTE) return;
    const float4* x4 = (const float4*)(ing ? x_ing : x_taste);
    float4 vv = ing ? ((const float4*)g_v_src)[lane] : ((const float4*)g_v_dst)[lane];
    float  cc = ing ? g_c_src : g_c_dst;
    float* outp = ing ? g_a_src : g_a_dst;
    float4 xv[4];
    #pragma unroll
    for (int r = 0; r < 4; r++) xv[r] = x4[(size_t)(base + r) * 32 + lane];
    #pragma unroll
    for (int r = 0; r < 4; r++) {
        float s = xv[r].x * vv.x + xv[r].y * vv.y + xv[r].z * vv.z + xv[r].w * vv.w;
        #pragma unroll
        for (int o = 16; o; o >>= 1) s += __shfl_down_sync(0xffffffffu, s, o);
        if (lane == 0) outp[base + r] = s + cc;
    }
}

// ---------------- stream B: split W, zero counters, out_ing copy -----------
__global__ void k_splitW(const float* __restrict__ W) {
    int i = blockIdx.x * blockDim.x + threadIdx.x;
    if (i >= D * D) return;
    unsigned hi, lo;
    split_tf32(W[i], hi, lo);
    g_whi[i] = __uint_as_float(hi);
    g_wlo[i] = __uint_as_float(lo);
}

__global__ void k_zero() {
    int i = blockIdx.x * blockDim.x + threadIdx.x;
    if (i < N_TASTE) g_cnt[i] = 0;
}

__global__ void k_copy(const float4* __restrict__ src, float4* __restrict__ dst) {
    int i = blockIdx.x * blockDim.x + threadIdx.x;
    int n = N_ING * 32;
    int stride = gridDim.x * blockDim.x;
    for (; i < n; i += stride) dst[i] = src[i];
}

// ---------------- fill: bucket edges, packed 8B stores ---------------------
__global__ void k_fill(const int* __restrict__ src, const int* __restrict__ dst) {
    int e = blockIdx.x * blockDim.x + threadIdx.x;
    if (e >= E_EDGES) return;
    int si = src[e];
    int t  = dst[e];
    float l = g_a_src[si] + g_a_dst[t];
    l = l > 0.f ? l : NEG_SLOPE * l;
    int pos = atomicAdd(&g_cnt[t], 1);
    g_slot[(size_t)t * CAP + pos] = make_int2(si, __float_as_int(__expf(l)));
}

// ---------------- k_agg: gather-only, zero smem, max occupancy -------------
// warp per dst (grid-stride); normalized row -> g_gbuf
__global__ void __launch_bounds__(256) k_agg(const float* __restrict__ x_ing) {
    int gw    = (blockIdx.x * blockDim.x + threadIdx.x) >> 5;
    int lane  = threadIdx.x & 31;
    int nwarp = (gridDim.x * blockDim.x) >> 5;
    const float4* x4 = (const float4*)x_ing;
    float4* gb4 = (float4*)g_gbuf;
    for (int t = gw; t < N_TASTE; t += nwarp) {
        int n = g_cnt[t];
        const int2* sp = g_slot + (size_t)t * CAP;
        float4 acc = make_float4(0.f, 0.f, 0.f, 0.f);
        float wsum = 0.f;
        int e = 0;
        for (; e + 4 <= n; e += 4) {
            int2 e0 = sp[e], e1 = sp[e+1], e2 = sp[e+2], e3 = sp[e+3];
            float w0 = __int_as_float(e0.y), w1 = __int_as_float(e1.y);
            float w2 = __int_as_float(e2.y), w3 = __int_as_float(e3.y);
            float4 v0 = x4[(size_t)e0.x * 32 + lane];
            float4 v1 = x4[(size_t)e1.x * 32 + lane];
            float4 v2 = x4[(size_t)e2.x * 32 + lane];
            float4 v3 = x4[(size_t)e3.x * 32 + lane];
            wsum  += w0 + w1 + w2 + w3;
            acc.x += w0*v0.x + w1*v1.x + w2*v2.x + w3*v3.x;
            acc.y += w0*v0.y + w1*v1.y + w2*v2.y + w3*v3.y;
            acc.z += w0*v0.z + w1*v1.z + w2*v2.z + w3*v3.z;
            acc.w += w0*v0.w + w1*v1.w + w2*v2.w + w3*v3.w;
        }
        for (; e < n; e++) {
            int2 ee = sp[e];
            float w = __int_as_float(ee.y);
            float4 v = x4[(size_t)ee.x * 32 + lane];
            wsum += w;
            acc.x += w*v.x; acc.y += w*v.y; acc.z += w*v.z; acc.w += w*v.w;
        }
        float inv = 1.f / (wsum + 1e-16f);
        acc.x *= inv; acc.y *= inv; acc.z *= inv; acc.w *= inv;
        gb4[(size_t)t * 32 + lane] = acc;
    }
}

// ---------------- k_gemm: TF32 3-pass MMA, W hi/lo in smem -----------------
// TM=128 rows/block, warp owns 16 rows x 128 cols. A-frags via LDG from g_gbuf.
#define TM 128
#define SROW 132
__global__ void __launch_bounds__(256) k_gemm(const float* __restrict__ bias,
                                              const float* __restrict__ x_taste,
                                              float* __restrict__ out_taste) {
    extern __shared__ float sm[];
    float* whs = sm;                    // [128][SROW] hi
    float* wls = sm + D * SROW;         // [128][SROW] lo
    int tid  = threadIdx.x;
    int lane = tid & 31;
    int wrp  = tid >> 5;
    int row0 = blockIdx.x * TM;

    for (int i = tid; i < D * D; i += 256) {
        int k = i >> 7, n = i & 127;
        whs[k * SROW + n] = g_whi[i];
        wls[k * SROW + n] = g_wlo[i];
    }
    __syncthreads();

    int g = lane >> 2, t4 = lane & 3;
    int rbase = wrp * 16;
    int r0 = row0 + rbase + g;
    int r1 = r0 + 8;
    bool v0 = r0 < N_TASTE, v1 = r1 < N_TASTE;
    const float* A0 = g_gbuf + (size_t)(v0 ? r0 : 0) * D;
    const float* A1 = g_gbuf + (size_t)(v1 ? r1 : 0) * D;

    float acc[16][4];
    #pragma unroll
    for (int nn = 0; nn < 16; nn++)
        #pragma unroll
        for (int j = 0; j < 4; j++) acc[nn][j] = 0.f;

    #pragma unroll 1
    for (int kk = 0; kk < 16; kk++) {
        int k0 = kk * 8;
        float a0f = v0 ? A0[k0 + t4    ] : 0.f;
        float a2f = v0 ? A0[k0 + t4 + 4] : 0.f;
        float a1f = v1 ? A1[k0 + t4    ] : 0.f;
        float a3f = v1 ? A1[k0 + t4 + 4] : 0.f;
        unsigned a0h,a0l,a1h,a1l,a2h,a2l,a3h,a3l;
        split_tf32(a0f, a0h, a0l);
        split_tf32(a1f, a1h, a1l);
        split_tf32(a2f, a2h, a2l);
        split_tf32(a3f, a3h, a3l);
        #pragma unroll
        for (int nn = 0; nn < 16; nn++) {
            int col = nn * 8 + g;
            unsigned b0h = __float_as_uint(whs[(k0 + t4    ) * SROW + col]);
            unsigned b1h = __float_as_uint(whs[(k0 + t4 + 4) * SROW + col]);
            unsigned b0l = __float_as_uint(wls[(k0 + t4    ) * SROW + col]);
            unsigned b1l = __float_as_uint(wls[(k0 + t4 + 4) * SROW + col]);
            mma_tf32(acc[nn], a0h,a1h,a2h,a3h, b0h,b1h);   // hi*hi
            mma_tf32(acc[nn], a0h,a1h,a2h,a3h, b0l,b1l);   // hi*lo
            mma_tf32(acc[nn], a0l,a1l,a2l,a3l, b0h,b1h);   // lo*hi
        }
    }

    // ---- epilogue: relu + blend ----
    float has0 = (v0 && g_cnt[r0] > 0) ? 1.f : 0.f;
    float has1 = (v1 && g_cnt[r1] > 0) ? 1.f : 0.f;
    #pragma unroll
    for (int nn = 0; nn < 16; nn++) {
        int col = nn * 8 + 2 * t4;
        float2 bj = *(const float2*)(bias + col);
        if (v0) {
            float2 xt = *(const float2*)(x_taste + (size_t)r0 * D + col);
            float2 o;
            o.x = fmaxf(has0 * (acc[nn][0] + bj.x), 0.f) * 0.5f + 0.5f * xt.x;
            o.y = fmaxf(has0 * (acc[nn][1] + bj.y), 0.f) * 0.5f + 0.5f * xt.y;
            *(float2*)(out_taste + (size_t)r0 * D + col) = o;
        }
        if (v1) {
            float2 xt = *(const float2*)(x_taste + (size_t)r1 * D + col);
            float2 o;
            o.x = fmaxf(has1 * (acc[nn][2] + bj.x), 0.f) * 0.5f + 0.5f * xt.x;
            o.y = fmaxf(has1 * (acc[nn][3] + bj.y), 0.f) * 0.5f + 0.5f * xt.y;
            *(float2*)(out_taste + (size_t)r1 * D + col) = o;
        }
    }
}

// ---------------- launcher (fork/join capture pattern) ----------------
extern "C" void kernel_launch(void* const* d_in, const int* in_sizes, int n_in,
                              void* d_out, int out_size) {
    const float* x_ing   = (const float*)d_in[0];
    const float* x_taste = (const float*)d_in[1];
    const float* W_ing   = (const float*)d_in[2];
    const float* b_ing   = (const float*)d_in[3];
    const float* W_taste = (const float*)d_in[4];
    const float* b_taste = (const float*)d_in[5];
    const float* att_src = (const float*)d_in[6];
    const float* att_dst = (const float*)d_in[7];
    // d_in[8..10] (Wk, bk, q): softmax over single metapath == 1.0 -> dead code
    const int* src_idx = (const int*)d_in[11];
    const int* dst_idx = (const int*)d_in[12];

    float* out       = (float*)d_out;
    float* out_ing   = out;                      // [N_ING, D] == x_ing
    float* out_taste = out + (size_t)N_ING * D;  // [N_TASTE, D]

    static const int SMEM_GEMM = 2 * D * SROW * (int)sizeof(float);  // 135168

    static cudaStream_t sB = nullptr;
    static cudaEvent_t  evFork = nullptr, evZero = nullptr, evCopy = nullptr;
    if (sB == nullptr) {
        cudaStreamCreateWithFlags(&sB, cudaStreamNonBlocking);
        cudaEventCreateWithFlags(&evFork, cudaEventDisableTiming);
        cudaEventCreateWithFlags(&evZero, cudaEventDisableTiming);
        cudaEventCreateWithFlags(&evCopy, cudaEventDisableTiming);
        cudaFuncSetAttribute(k_gemm, cudaFuncAttributeMaxDynamicSharedMemorySize, SMEM_GEMM);
    }

    // fork stream B: W split + zero counters + out_ing copy (all off critical path)
    cudaEventRecord(evFork, 0);
    cudaStreamWaitEvent(sB, evFork, 0);
    k_splitW<<<(D * D + 255) / 256, 256, 0, sB>>>(W_ing);
    k_zero<<<(N_TASTE + 1023) / 1024, 1024, 0, sB>>>();
    cudaEventRecord(evZero, sB);                 // covers splitW + zero
    k_copy<<<1024, 256, 0, sB>>>((const float4*)x_ing, (float4*)out_ing);
    cudaEventRecord(evCopy, sB);

    // stream A (default): critical path
    k0_prep<<<33, 256>>>(W_ing, b_ing, W_taste, b_taste, att_src, att_dst);
    k_dots<<<4688, 256>>>(x_ing, x_taste);
    cudaStreamWaitEvent(0, evZero, 0);
    k_fill<<<(E_EDGES + 255) / 256, 256>>>(src_idx, dst_idx);
    k_agg<<<888, 256>>>(x_ing);
    k_gemm<<<(N_TASTE + TM - 1) / TM, 256, SMEM_GEMM>>>(b_ing, x_taste, out_taste);
    cudaStreamWaitEvent(0, evCopy, 0);           // join copy before graph end
}